// round 8
// baseline (speedup 1.0000x reference)
#include <cuda_runtime.h>
#include <cuda_bf16.h>

// SingleRoIExtractor: FPN RoIAlign (aligned=False), out 7x7, sr=2.
// R7: R6 (register geometry, 4 channels/thread) restructured sample-outer
// with unroll-1 so geometry is transient -> ~40 regs -> ~75% occupancy.

#define OUTS   7
#define CH     256
#define BINS   (OUTS * OUTS)            // 49
#define PER_ROI (CH * BINS)             // 12544
#define CPT    4                        // channels per thread
#define CGRP   (CH / CPT)               // 64
#define THR_PER_ROI (CGRP * BINS)       // 3136
#define BLK    224
#define BLOCKS_PER_ROI (THR_PER_ROI / BLK)   // 14

__global__ void __launch_bounds__(BLK, 7)
roi_extract_kernel(const float* __restrict__ f0,
                   const float* __restrict__ f1,
                   const float* __restrict__ f2,
                   const float* __restrict__ f3,
                   const float* __restrict__ rois,
                   float* __restrict__ out)
{
    const int n     = blockIdx.x / BLOCKS_PER_ROI;
    const int blk   = blockIdx.x % BLOCKS_PER_ROI;
    const int local = blk * BLK + threadIdx.x;      // [0, 3136)
    const int c0    = local / BINS;                 // [0, 64)
    const int bin   = local - c0 * BINS;            // [0, 49)
    const int ph    = bin / OUTS;
    const int pw    = bin - ph * OUTS;

    // ---- per-RoI params ----
    const float rb  = __ldg(rois + n * 5 + 0);
    const float rx1 = __ldg(rois + n * 5 + 1);
    const float ry1 = __ldg(rois + n * 5 + 2);
    const float rx2 = __ldg(rois + n * 5 + 3);
    const float ry2 = __ldg(rois + n * 5 + 4);

    const float sc = sqrtf((rx2 - rx1 + 1.0f) * (ry2 - ry1 + 1.0f));
    int lvl = (int)floorf(log2f(sc * (1.0f / 56.0f) + 1e-6f));
    lvl = lvl < 0 ? 0 : (lvl > 3 ? 3 : lvl);

    const float* f; int H, W; float ss;
    if      (lvl == 0) { f = f0; H = 200; W = 304; ss = 0.25f;    }
    else if (lvl == 1) { f = f1; H = 100; W = 152; ss = 0.125f;   }
    else if (lvl == 2) { f = f2; H = 50;  W = 76;  ss = 0.0625f;  }
    else               { f = f3; H = 25;  W = 38;  ss = 0.03125f; }

    const int   b    = (int)rb;
    const int   HW   = H * W;
    const float x1   = rx1 * ss, y1 = ry1 * ss;
    const float binw = fmaxf(rx2 * ss - x1, 1.0f) * (1.0f / OUTS);
    const float binh = fmaxf(ry2 * ss - y1, 1.0f) * (1.0f / OUTS);
    const float Hf = (float)H, Wf = (float)W;

    const float* __restrict__ fc0 = f + (size_t)b * CH * HW + (size_t)c0 * HW;
    const size_t cstep = (size_t)CGRP * HW;

    float acc0 = 0.0f, acc1 = 0.0f, acc2 = 0.0f, acc3 = 0.0f;

    // sample-outer, NOT unrolled: geometry regs live only inside the body
    #pragma unroll 1
    for (int s = 0; s < 4; ++s) {
        const int iy = s >> 1, ix = s & 1;
        const float y = y1 + ((float)(ph * 2 + iy) + 0.5f) * 0.5f * binh;
        const float x = x1 + ((float)(pw * 2 + ix) + 0.5f) * 0.5f * binw;
        const bool valid = (y >= -1.0f) & (y <= Hf) & (x >= -1.0f) & (x <= Wf);

        const float yc = fminf(fmaxf(y, 0.0f), Hf - 1.0f);
        const float xc = fminf(fmaxf(x, 0.0f), Wf - 1.0f);
        const int   yi = (int)yc;
        const int   xi = (int)xc;
        const float ly = yc - (float)yi;
        const float lx = xc - (float)xi;
        const int   yB = min(yi + 1, H - 1);
        const int   xB = min(xi + 1, W - 1);

        const float vmul = valid ? 0.25f : 0.0f;   // fold 1/4 sample mean
        const float wy0 = (1.0f - ly) * vmul;
        const float wy1 = ly * vmul;
        const float w00 = wy0 * (1.0f - lx);
        const float w01 = wy0 * lx;
        const float w10 = wy1 * (1.0f - lx);
        const float w11 = wy1 * lx;

        const int o00 = yi * W + xi, o01 = yi * W + xB;
        const int o10 = yB * W + xi, o11 = yB * W + xB;

        // 16 independent LDGs (4 taps x 4 channels)
        const float* __restrict__ fa = fc0;
        const float* __restrict__ fb = fc0 + cstep;
        const float* __restrict__ fcc = fc0 + 2 * cstep;
        const float* __restrict__ fd = fc0 + 3 * cstep;

        acc0 += __ldg(fa + o00) * w00 + __ldg(fa + o01) * w01
              + __ldg(fa + o10) * w10 + __ldg(fa + o11) * w11;
        acc1 += __ldg(fb + o00) * w00 + __ldg(fb + o01) * w01
              + __ldg(fb + o10) * w10 + __ldg(fb + o11) * w11;
        acc2 += __ldg(fcc + o00) * w00 + __ldg(fcc + o01) * w01
              + __ldg(fcc + o10) * w10 + __ldg(fcc + o11) * w11;
        acc3 += __ldg(fd + o00) * w00 + __ldg(fd + o01) * w01
              + __ldg(fd + o10) * w10 + __ldg(fd + o11) * w11;
    }

    float* __restrict__ po = out + (size_t)n * PER_ROI + (size_t)c0 * BINS + bin;
    const size_t ostep = (size_t)CGRP * BINS;
    __stcs(po,             acc0);
    __stcs(po +     ostep, acc1);
    __stcs(po + 2 * ostep, acc2);
    __stcs(po + 3 * ostep, acc3);
}

extern "C" void kernel_launch(void* const* d_in, const int* in_sizes, int n_in,
                              void* d_out, int out_size)
{
    const float* f0   = (const float*)d_in[0];
    const float* f1   = (const float*)d_in[1];
    const float* f2   = (const float*)d_in[2];
    const float* f3   = (const float*)d_in[3];
    const float* rois = (const float*)d_in[4];
    float* out = (float*)d_out;

    const int K = in_sizes[4] / 5;
    roi_extract_kernel<<<K * BLOCKS_PER_ROI, BLK>>>(f0, f1, f2, f3, rois, out);
}